// round 13
// baseline (speedup 1.0000x reference)
#include <cuda_runtime.h>

#define NN 50000
#define EE 800000
#define HH 64
#define KIN 128
#define ET (EE + NN)
#define NSCAN_BLK 196                 // 196*256 = 50176 >= NN+1

// ---------------- scratch (static __device__ globals; allocation-free) ------
__device__ __align__(16) float g_h[NN * HH];     // layer projection h
__device__ __align__(16) float g_xp[NN * HH];    // current node features
__device__ __align__(16) float g_res[NN * HH];   // residual projection
__device__ __align__(16) float g_as[NN];
__device__ __align__(16) float g_ad[NN];
__device__ __align__(16) float g_poolp[6250 * HH];

// CSR scratch
__device__ int g_deg[NN + 1];
__device__ int g_rowptr[NN + 1];
__device__ int g_cursor[NN];
__device__ int g_csr_src[ET];
__device__ int g_btot[NSCAN_BLK];
__device__ int g_boff[NSCAN_BLK];

// ---------------- f32x2 packed helpers (sm_103a) -----------------------------
typedef unsigned long long ull;

__device__ __forceinline__ void ffma2(ull& d, ull a, ull b) {
    asm("fma.rn.f32x2 %0, %1, %2, %0;" : "+l"(d) : "l"(a), "l"(b));
}
__device__ __forceinline__ ull fadd2(ull a, ull b) {
    ull r;
    asm("add.rn.f32x2 %0, %1, %2;" : "=l"(r) : "l"(a), "l"(b));
    return r;
}
__device__ __forceinline__ ull pack2(float x) {
    ull r; unsigned u = __float_as_uint(x);
    asm("mov.b64 %0, {%1, %2};" : "=l"(r) : "r"(u), "r"(u));
    return r;
}
__device__ __forceinline__ void unpack2(ull v, float& lo, float& hi) {
    unsigned a, b;
    asm("mov.b64 {%0, %1}, %2;" : "=r"(a), "=r"(b) : "l"(v));
    lo = __uint_as_float(a); hi = __uint_as_float(b);
}

// ---------------- CSR build --------------------------------------------------
__global__ void deg_init() {
    int i = blockIdx.x * blockDim.x + threadIdx.x;
    if (i <= NN) g_deg[i] = (i < NN) ? 1 : 0;   // self-loop counted up front
}

__global__ void deg_count(const int* __restrict__ ei) {
    int i = blockIdx.x * blockDim.x + threadIdx.x;
    if (i >= EE) return;
    atomicAdd(&g_deg[ei[EE + i]], 1);
}

// phase 1: per-block exclusive scan (coalesced loads, shfl scans)
__global__ void scan_local() {
    __shared__ int wsum[8];
    int t = threadIdx.x;
    int idx = blockIdx.x * 256 + t;
    int d = (idx < NN) ? g_deg[idx] : 0;
    int v = d;
    #pragma unroll
    for (int o = 1; o < 32; o <<= 1) {
        int u = __shfl_up_sync(0xffffffffu, v, o);
        if ((t & 31) >= o) v += u;
    }
    if ((t & 31) == 31) wsum[t >> 5] = v;
    __syncthreads();
    if (t < 32) {
        int w = (t < 8) ? wsum[t] : 0;
        #pragma unroll
        for (int o = 1; o < 8; o <<= 1) {
            int u = __shfl_up_sync(0xffffffffu, w, o);
            if (t >= o) w += u;
        }
        if (t < 8) wsum[t] = w;          // inclusive warp totals
    }
    __syncthreads();
    int excl = v - d + ((t >> 5) ? wsum[(t >> 5) - 1] : 0);
    if (idx <= NN) g_rowptr[idx] = excl;
    if (t == 255) g_btot[blockIdx.x] = wsum[7];
}

// phase 2: single-block exclusive scan of the 196 block totals
__global__ void scan_tot() {
    __shared__ int wsum[8];
    int t = threadIdx.x;
    int d = (t < NSCAN_BLK) ? g_btot[t] : 0;
    int v = d;
    #pragma unroll
    for (int o = 1; o < 32; o <<= 1) {
        int u = __shfl_up_sync(0xffffffffu, v, o);
        if ((t & 31) >= o) v += u;
    }
    if ((t & 31) == 31) wsum[t >> 5] = v;
    __syncthreads();
    if (t < 32) {
        int w = (t < 8) ? wsum[t] : 0;
        #pragma unroll
        for (int o = 1; o < 8; o <<= 1) {
            int u = __shfl_up_sync(0xffffffffu, w, o);
            if (t >= o) w += u;
        }
        if (t < 8) wsum[t] = w;
    }
    __syncthreads();
    int excl = v - d + ((t >> 5) ? wsum[(t >> 5) - 1] : 0);
    if (t < NSCAN_BLK) g_boff[t] = excl;
}

// phase 3: add block offsets + (fused) cursor/self-loop init
__global__ void scan_add() {
    int t = threadIdx.x;
    int idx = blockIdx.x * 256 + t;
    if (idx > NN) return;
    int r = g_rowptr[idx] + g_boff[blockIdx.x];
    g_rowptr[idx] = r;
    if (idx < NN) {
        g_csr_src[r] = idx;              // self loop first
        g_cursor[idx] = r + 1;
    }
}

__global__ void csr_fill(const int* __restrict__ ei) {
    int i = blockIdx.x * blockDim.x + threadIdx.x;
    if (i >= EE) return;
    int s = ei[i], d = ei[EE + i];
    int pos = atomicAdd(&g_cursor[d], 1);
    g_csr_src[pos] = s;
}

// ---------------- conv1 GEMM: x[N,128] x W[128,64] -> g_h, g_as, g_ad --------
__global__ void gemm_conv1(const float* __restrict__ A,
                           const float* __restrict__ W,
                           const float* __restrict__ av,
                           const float* __restrict__ adv) {
    extern __shared__ float sm[];
    float* Ws  = sm;                 // [128][64]
    float* Ast = sm + KIN * 64;      // [128][66]
    const int AST = 66;

    int tid = threadIdx.x;
    int tx = tid & 15;
    int ty = tid >> 4;

    for (int i = tid; i < KIN * 64; i += 128) Ws[i] = W[i];
    int nbase = blockIdx.x * 64;
    for (int i = tid; i < 64 * KIN; i += 128) {
        int node = i / KIN, k = i % KIN;
        int n = nbase + node;
        Ast[k * AST + node] = (n < NN) ? A[n * KIN + k] : 0.f;
    }
    __syncthreads();

    ull acc[4][4];
    #pragma unroll
    for (int p = 0; p < 4; p++)
        #pragma unroll
        for (int c = 0; c < 4; c++) acc[p][c] = 0ull;

    #pragma unroll 4
    for (int k = 0; k < KIN; k++) {
        float4 wv = *(const float4*)&Ws[k * 64 + tx * 4];
        ull w0 = pack2(wv.x), w1 = pack2(wv.y), w2 = pack2(wv.z), w3 = pack2(wv.w);
        #pragma unroll
        for (int p = 0; p < 4; p++) {
            int pair = ty + 8 * p;
            ull ap = *(const ull*)&Ast[k * AST + 2 * pair];
            ffma2(acc[p][0], ap, w0);
            ffma2(acc[p][1], ap, w1);
            ffma2(acc[p][2], ap, w2);
            ffma2(acc[p][3], ap, w3);
        }
    }

    float4 a4  = *(const float4*)&av[tx * 4];
    float4 ad4 = *(const float4*)&adv[tx * 4];
    #pragma unroll
    for (int p = 0; p < 4; p++) {
        int n0 = nbase + 2 * (ty + 8 * p);
        bool ok0 = n0 < NN;
        bool ok1 = (n0 + 1) < NN;
        #pragma unroll
        for (int c = 0; c < 4; c++) {
            float v0, v1;
            unpack2(acc[p][c], v0, v1);
            int col = tx * 4 + c;
            if (ok0) g_h[n0 * 64 + col] = v0;
            if (ok1) g_h[(n0 + 1) * 64 + col] = v1;
        }
        ull pa = 0ull, pd = 0ull;
        ffma2(pa, acc[p][0], pack2(a4.x));  ffma2(pa, acc[p][1], pack2(a4.y));
        ffma2(pa, acc[p][2], pack2(a4.z));  ffma2(pa, acc[p][3], pack2(a4.w));
        ffma2(pd, acc[p][0], pack2(ad4.x)); ffma2(pd, acc[p][1], pack2(ad4.y));
        ffma2(pd, acc[p][2], pack2(ad4.z)); ffma2(pd, acc[p][3], pack2(ad4.w));
        #pragma unroll
        for (int off = 8; off > 0; off >>= 1) {
            pa = fadd2(pa, __shfl_xor_sync(0xffffffffu, pa, off));
            pd = fadd2(pd, __shfl_xor_sync(0xffffffffu, pd, off));
        }
        if (tx == 0) {
            float a0, a1, d0, d1;
            unpack2(pa, a0, a1);
            unpack2(pd, d0, d1);
            if (ok0) { g_as[n0] = a0; g_ad[n0] = d0; }
            if (ok1) { g_as[n0 + 1] = a1; g_ad[n0 + 1] = d1; }
        }
    }
}

// ---------------- layer GEMM: g_xp[N,64] x [convW|projW][64,128] -------------
__global__ void gemm_layer(const float* __restrict__ CW,
                           const float* __restrict__ PW,
                           const float* __restrict__ av,
                           const float* __restrict__ adv) {
    extern __shared__ float sm[];
    float* Ws  = sm;                 // [64][128]
    float* Ast = sm + HH * 128;      // [64][66]
    const int AST = 66;

    int tid = threadIdx.x;
    int tx = tid & 31;
    int ty = tid >> 5;

    for (int i = tid; i < HH * 128; i += 256) {
        int k = i >> 7, c = i & 127;
        Ws[i] = (c < 64) ? CW[k * 64 + c] : PW[k * 64 + (c - 64)];
    }
    int nbase = blockIdx.x * 64;
    for (int i = tid; i < 64 * HH; i += 256) {
        int node = i >> 6, k = i & 63;
        int n = nbase + node;
        Ast[k * AST + node] = (n < NN) ? g_xp[n * 64 + k] : 0.f;
    }
    __syncthreads();

    ull acc[4][4];
    #pragma unroll
    for (int p = 0; p < 4; p++)
        #pragma unroll
        for (int c = 0; c < 4; c++) acc[p][c] = 0ull;

    #pragma unroll 4
    for (int k = 0; k < HH; k++) {
        float4 wv = *(const float4*)&Ws[k * 128 + tx * 4];
        ull w0 = pack2(wv.x), w1 = pack2(wv.y), w2 = pack2(wv.z), w3 = pack2(wv.w);
        #pragma unroll
        for (int p = 0; p < 4; p++) {
            int pair = ty + 8 * p;
            ull ap = *(const ull*)&Ast[k * AST + 2 * pair];
            ffma2(acc[p][0], ap, w0);
            ffma2(acc[p][1], ap, w1);
            ffma2(acc[p][2], ap, w2);
            ffma2(acc[p][3], ap, w3);
        }
    }

    bool is_h = (tx < 16);
    float4 a4  = make_float4(0.f, 0.f, 0.f, 0.f);
    float4 ad4 = make_float4(0.f, 0.f, 0.f, 0.f);
    if (is_h) {
        a4  = *(const float4*)&av[tx * 4];
        ad4 = *(const float4*)&adv[tx * 4];
    }
    #pragma unroll
    for (int p = 0; p < 4; p++) {
        int n0 = nbase + 2 * (ty + 8 * p);
        bool ok0 = n0 < NN;
        bool ok1 = (n0 + 1) < NN;
        #pragma unroll
        for (int c = 0; c < 4; c++) {
            float v0, v1;
            unpack2(acc[p][c], v0, v1);
            int col = tx * 4 + c;
            float* dst = is_h ? &g_h[0] + n0 * 64 + col
                              : &g_res[0] + n0 * 64 + (col - 64);
            if (ok0) dst[0] = v0;
            if (ok1) dst[64] = v1;
        }
        ull pa = 0ull, pd = 0ull;
        if (is_h) {
            ffma2(pa, acc[p][0], pack2(a4.x));  ffma2(pa, acc[p][1], pack2(a4.y));
            ffma2(pa, acc[p][2], pack2(a4.z));  ffma2(pa, acc[p][3], pack2(a4.w));
            ffma2(pd, acc[p][0], pack2(ad4.x)); ffma2(pd, acc[p][1], pack2(ad4.y));
            ffma2(pd, acc[p][2], pack2(ad4.z)); ffma2(pd, acc[p][3], pack2(ad4.w));
        }
        #pragma unroll
        for (int off = 16; off > 0; off >>= 1) {
            pa = fadd2(pa, __shfl_xor_sync(0xffffffffu, pa, off));
            pd = fadd2(pd, __shfl_xor_sync(0xffffffffu, pd, off));
        }
        if (tx == 0) {
            float a0, a1, d0, d1;
            unpack2(pa, a0, a1);
            unpack2(pd, d0, d1);
            if (ok0) { g_as[n0] = a0; g_ad[n0] = d0; }
            if (ok1) { g_as[n0 + 1] = a1; g_ad[n0 + 1] = d1; }
        }
    }
}

// ---------------- fused GAT: software-pipelined aggregation ------------------
// One warp per destination node. Double-buffered: batch j+1's loads are issued
// BEFORE batch j's FMAs consume their data -> ~2x in-flight memory per warp.
template <int FIRST, int POOL>
__global__ void gat_agg(const float* __restrict__ cb,
                        const float* __restrict__ pb,
                        const float* __restrict__ bg, const float* __restrict__ bb,
                        const float* __restrict__ bm, const float* __restrict__ bv) {
    __shared__ float sp[POOL ? 512 : 1];
    int warp = (blockIdx.x * blockDim.x + threadIdx.x) >> 5;
    int lane = threadIdx.x & 31;
    int beg = g_rowptr[warp];
    int end = g_rowptr[warp + 1];
    float adv = g_ad[warp];

    float s = 0.f;
    float2 acc = make_float2(0.f, 0.f);
    int fo = lane * 2;
    int j = beg;
    int jend4 = beg + ((end - beg) & ~3);

    // pipelined state: weights + h rows of the "current" batch
    float w0, w1, w2, w3;
    float2 h0, h1, h2, h3;

    #define LOADB(JJ, W0, W1, W2, W3, H0, H1, H2, H3)                          \
        {                                                                      \
            int s0 = g_csr_src[(JJ)];                                          \
            int s1 = g_csr_src[(JJ) + 1];                                      \
            int s2 = g_csr_src[(JJ) + 2];                                      \
            int s3 = g_csr_src[(JJ) + 3];                                      \
            float a0 = g_as[s0];                                               \
            float a1 = g_as[s1];                                               \
            float a2 = g_as[s2];                                               \
            float a3 = g_as[s3];                                               \
            H0 = *(const float2*)&g_h[s0 * 64 + fo];                           \
            H1 = *(const float2*)&g_h[s1 * 64 + fo];                           \
            H2 = *(const float2*)&g_h[s2 * 64 + fo];                           \
            H3 = *(const float2*)&g_h[s3 * 64 + fo];                           \
            float e0 = a0 + adv; e0 = e0 > 0.f ? e0 : 0.2f * e0;               \
            float e1 = a1 + adv; e1 = e1 > 0.f ? e1 : 0.2f * e1;               \
            float e2 = a2 + adv; e2 = e2 > 0.f ? e2 : 0.2f * e2;               \
            float e3 = a3 + adv; e3 = e3 > 0.f ? e3 : 0.2f * e3;               \
            W0 = __expf(e0); W1 = __expf(e1); W2 = __expf(e2); W3 = __expf(e3);\
        }

    #define CONSB(W0, W1, W2, W3, H0, H1, H2, H3)                              \
        {                                                                      \
            s += (W0 + W1) + (W2 + W3);                                        \
            acc.x += W0 * H0.x; acc.y += W0 * H0.y;                            \
            acc.x += W1 * H1.x; acc.y += W1 * H1.y;                            \
            acc.x += W2 * H2.x; acc.y += W2 * H2.y;                            \
            acc.x += W3 * H3.x; acc.y += W3 * H3.y;                            \
        }

    if (j < jend4) {
        LOADB(j, w0, w1, w2, w3, h0, h1, h2, h3);
        j += 4;
        for (; j < jend4; j += 4) {
            float nw0, nw1, nw2, nw3;
            float2 nh0, nh1, nh2, nh3;
            LOADB(j, nw0, nw1, nw2, nw3, nh0, nh1, nh2, nh3);
            CONSB(w0, w1, w2, w3, h0, h1, h2, h3);
            w0 = nw0; w1 = nw1; w2 = nw2; w3 = nw3;
            h0 = nh0; h1 = nh1; h2 = nh2; h3 = nh3;
        }
        CONSB(w0, w1, w2, w3, h0, h1, h2, h3);
    }
    for (; j < end; j++) {
        int s0 = g_csr_src[j];
        float e0 = g_as[s0] + adv; e0 = e0 > 0.f ? e0 : 0.2f * e0;
        float ww = __expf(e0);
        float2 hh = *(const float2*)&g_h[s0 * 64 + fo];
        s += ww;
        acc.x += ww * hh.x;
        acc.y += ww * hh.y;
    }
    #undef LOADB
    #undef CONSB

    float inv = 1.f / (s + 1e-16f);
    acc.x *= inv;
    acc.y *= inv;

    int f = fo;
    float v0 = fmaxf(acc.x + cb[f],     0.f);
    float v1 = fmaxf(acc.y + cb[f + 1], 0.f);
    v0 = (v0 - bm[f])     * rsqrtf(bv[f]     + 1e-5f) * bg[f]     + bb[f];
    v1 = (v1 - bm[f + 1]) * rsqrtf(bv[f + 1] + 1e-5f) * bg[f + 1] + bb[f + 1];
    if (!FIRST) {
        float2 rv = *(const float2*)&g_res[warp * 64 + f];
        v0 += rv.x + pb[f];
        v1 += rv.y + pb[f + 1];
    }
    *(float2*)&g_xp[warp * 64 + f] = make_float2(v0, v1);

    if (POOL) {
        int w = threadIdx.x >> 5;
        sp[w * 64 + f] = v0;
        sp[w * 64 + f + 1] = v1;
        __syncthreads();
        int t = threadIdx.x;
        if (t < 64) {
            float ps = 0.f;
            #pragma unroll
            for (int k = 0; k < 8; k++) ps += sp[k * 64 + t];
            g_poolp[blockIdx.x * 64 + t] = ps;
        }
    }
}

// ---------------- head: sum pool partials + MLP ------------------------------
__global__ void head_k(const float* __restrict__ hW1, const float* __restrict__ hb1,
                       const float* __restrict__ hg, const float* __restrict__ hb,
                       const float* __restrict__ hm, const float* __restrict__ hv,
                       const float* __restrict__ hW2, const float* __restrict__ hb2,
                       float* __restrict__ out) {
    __shared__ float part[512];
    __shared__ float gs[64];
    __shared__ float hs[32];
    int t = threadIdx.x;
    int f = t & 63, g = t >> 6;              // 8 batches
    float s = 0.f;
    for (int b = g; b < 6250; b += 8)
        s += g_poolp[b * 64 + f];
    part[t] = s;
    __syncthreads();
    if (t < 64) {
        float tot = 0.f;
        #pragma unroll
        for (int k = 0; k < 8; k++) tot += part[k * 64 + t];
        gs[t] = tot * (1.0f / NN);
    }
    __syncthreads();
    if (t < 32) {
        float acc = hb1[t];
        #pragma unroll 16
        for (int ff = 0; ff < 64; ff++) acc += gs[ff] * hW1[ff * 32 + t];
        acc = fmaxf(acc, 0.f);
        acc = (acc - hm[t]) * rsqrtf(hv[t] + 1e-5f) * hg[t] + hb[t];
        hs[t] = acc * hW2[t];
    }
    __syncthreads();
    if (t == 0) {
        float ss = 0.f;
        for (int j = 0; j < 32; j++) ss += hs[j];
        out[0] = ss + hb2[0];
    }
}

// ---------------- launch ----------------------------------------------------
extern "C" void kernel_launch(void* const* d_in, const int* in_sizes, int n_in,
                              void* d_out, int out_size) {
    const float* x        = (const float*)d_in[0];
    const int*   ei       = (const int*)d_in[1];
    const float* conv1_W  = (const float*)d_in[2];
    const float* conv1_as = (const float*)d_in[3];
    const float* conv1_ad = (const float*)d_in[4];
    const float* conv1_b  = (const float*)d_in[5];
    const float* convW    = (const float*)d_in[6];
    const float* conv_as  = (const float*)d_in[7];
    const float* conv_ad  = (const float*)d_in[8];
    const float* conv_b   = (const float*)d_in[9];
    const float* bn_g     = (const float*)d_in[10];
    const float* bn_b     = (const float*)d_in[11];
    const float* bn_m     = (const float*)d_in[12];
    const float* bn_v     = (const float*)d_in[13];
    const float* projW    = (const float*)d_in[14];
    const float* projb    = (const float*)d_in[15];
    const float* hW1      = (const float*)d_in[16];
    const float* hb1      = (const float*)d_in[17];
    const float* hbn_g    = (const float*)d_in[18];
    const float* hbn_b    = (const float*)d_in[19];
    const float* hbn_m    = (const float*)d_in[20];
    const float* hbn_v    = (const float*)d_in[21];
    const float* hW2      = (const float*)d_in[22];
    const float* hb2      = (const float*)d_in[23];
    float* out = (float*)d_out;

    const int NB_E    = (EE + 255) / 256;               // 3125
    const int NB_GEMM = (NN + 63) / 64;                 // 782
    const int NB_WARP = (NN * 32) / 256;                // 6250 (warp per node)

    const int SMEM_C1 = (KIN * 64 + KIN * 66) * 4;      // 66560 B
    const int SMEM_L  = (HH * 128 + HH * 66) * 4;       // 49664 B
    static int smem_set = 0;
    if (!smem_set) {
        cudaFuncSetAttribute(gemm_conv1, cudaFuncAttributeMaxDynamicSharedMemorySize, SMEM_C1);
        cudaFuncSetAttribute(gemm_layer, cudaFuncAttributeMaxDynamicSharedMemorySize, SMEM_L);
        smem_set = 1;
    }

    // ---- CSR build + conv1 GEMM interleaved ----
    // gemm_conv1 is CSR-independent; placed 4th so the ncu slot profiles it.
    deg_init<<<(NN + 256) / 256, 256>>>();
    deg_count<<<NB_E, 256>>>(ei);
    scan_local<<<NSCAN_BLK, 256>>>();
    gemm_conv1<<<NB_GEMM, 128, SMEM_C1>>>(x, conv1_W, conv1_as, conv1_ad);
    scan_tot<<<1, 256>>>();
    scan_add<<<NSCAN_BLK, 256>>>();
    csr_fill<<<NB_E, 256>>>(ei);

    // ---- conv1 aggregation ----
    gat_agg<1, 0><<<NB_WARP, 256>>>(conv1_b, nullptr, bn_g, bn_b, bn_m, bn_v);

    // ---- conv2..conv5 (pool fused into last agg) ----
    for (int l = 0; l < 4; l++) {
        gemm_layer<<<NB_GEMM, 256, SMEM_L>>>(convW + l * 4096, projW + l * 4096,
                                             conv_as + l * 64, conv_ad + l * 64);
        if (l < 3)
            gat_agg<0, 0><<<NB_WARP, 256>>>(conv_b + l * 64, projb + l * 64,
                                            bn_g + (l + 1) * 64, bn_b + (l + 1) * 64,
                                            bn_m + (l + 1) * 64, bn_v + (l + 1) * 64);
        else
            gat_agg<0, 1><<<NB_WARP, 256>>>(conv_b + l * 64, projb + l * 64,
                                            bn_g + (l + 1) * 64, bn_b + (l + 1) * 64,
                                            bn_m + (l + 1) * 64, bn_v + (l + 1) * 64);
    }

    // ---- head ----
    head_k<<<1, 512>>>(hW1, hb1, hbn_g, hbn_b, hbn_m, hbn_v, hW2, hb2, out);
}

// round 15
// speedup vs baseline: 1.5570x; 1.5570x over previous
#include <cuda_runtime.h>

#define NN 50000
#define EE 800000
#define HH 64
#define KIN 128
#define ET (EE + NN)
#define NSCAN_BLK 196                 // 196*256 = 50176 >= NN+1

// ---------------- scratch (static __device__ globals; allocation-free) ------
__device__ __align__(16) float g_h[NN * HH];     // layer projection h
__device__ __align__(16) float g_xp[NN * HH];    // current node features
__device__ __align__(16) float g_res[NN * HH];   // residual projection
__device__ __align__(16) float g_as[NN];
__device__ __align__(16) float g_ad[NN];
__device__ __align__(16) float g_poolp[6250 * HH];

// CSR scratch
__device__ int g_deg[NN + 1];
__device__ int g_rowptr[NN + 1];
__device__ int g_cursor[NN];
__device__ int g_csr_src[ET];
__device__ int g_btot[NSCAN_BLK];
__device__ int g_boff[NSCAN_BLK];

// ---------------- f32x2 packed helpers (sm_103a) -----------------------------
typedef unsigned long long ull;

__device__ __forceinline__ void ffma2(ull& d, ull a, ull b) {
    asm("fma.rn.f32x2 %0, %1, %2, %0;" : "+l"(d) : "l"(a), "l"(b));
}
__device__ __forceinline__ ull fadd2(ull a, ull b) {
    ull r;
    asm("add.rn.f32x2 %0, %1, %2;" : "=l"(r) : "l"(a), "l"(b));
    return r;
}
__device__ __forceinline__ ull pack2(float x) {
    ull r; unsigned u = __float_as_uint(x);
    asm("mov.b64 %0, {%1, %2};" : "=l"(r) : "r"(u), "r"(u));
    return r;
}
__device__ __forceinline__ void unpack2(ull v, float& lo, float& hi) {
    unsigned a, b;
    asm("mov.b64 {%0, %1}, %2;" : "=r"(a), "=r"(b) : "l"(v));
    lo = __uint_as_float(a); hi = __uint_as_float(b);
}

// ---------------- CSR build --------------------------------------------------
__global__ void deg_init() {
    int i = blockIdx.x * blockDim.x + threadIdx.x;
    if (i <= NN) g_deg[i] = (i < NN) ? 1 : 0;   // self-loop counted up front
}

__global__ void deg_count(const int* __restrict__ ei) {
    int i = blockIdx.x * blockDim.x + threadIdx.x;
    if (i >= EE) return;
    atomicAdd(&g_deg[ei[EE + i]], 1);
}

// phase 1: per-block exclusive scan (coalesced loads, shfl scans)
__global__ void scan_local() {
    __shared__ int wsum[8];
    int t = threadIdx.x;
    int idx = blockIdx.x * 256 + t;
    int d = (idx < NN) ? g_deg[idx] : 0;
    int v = d;
    #pragma unroll
    for (int o = 1; o < 32; o <<= 1) {
        int u = __shfl_up_sync(0xffffffffu, v, o);
        if ((t & 31) >= o) v += u;
    }
    if ((t & 31) == 31) wsum[t >> 5] = v;
    __syncthreads();
    if (t < 32) {
        int w = (t < 8) ? wsum[t] : 0;
        #pragma unroll
        for (int o = 1; o < 8; o <<= 1) {
            int u = __shfl_up_sync(0xffffffffu, w, o);
            if (t >= o) w += u;
        }
        if (t < 8) wsum[t] = w;          // inclusive warp totals
    }
    __syncthreads();
    int excl = v - d + ((t >> 5) ? wsum[(t >> 5) - 1] : 0);
    if (idx <= NN) g_rowptr[idx] = excl;
    if (t == 255) g_btot[blockIdx.x] = wsum[7];
}

// phase 2: single-block exclusive scan of the 196 block totals
__global__ void scan_tot() {
    __shared__ int wsum[8];
    int t = threadIdx.x;
    int d = (t < NSCAN_BLK) ? g_btot[t] : 0;
    int v = d;
    #pragma unroll
    for (int o = 1; o < 32; o <<= 1) {
        int u = __shfl_up_sync(0xffffffffu, v, o);
        if ((t & 31) >= o) v += u;
    }
    if ((t & 31) == 31) wsum[t >> 5] = v;
    __syncthreads();
    if (t < 32) {
        int w = (t < 8) ? wsum[t] : 0;
        #pragma unroll
        for (int o = 1; o < 8; o <<= 1) {
            int u = __shfl_up_sync(0xffffffffu, w, o);
            if (t >= o) w += u;
        }
        if (t < 8) wsum[t] = w;
    }
    __syncthreads();
    int excl = v - d + ((t >> 5) ? wsum[(t >> 5) - 1] : 0);
    if (t < NSCAN_BLK) g_boff[t] = excl;
}

// phase 3: add block offsets + (fused) cursor/self-loop init
__global__ void scan_add() {
    int t = threadIdx.x;
    int idx = blockIdx.x * 256 + t;
    if (idx > NN) return;
    int r = g_rowptr[idx] + g_boff[blockIdx.x];
    g_rowptr[idx] = r;
    if (idx < NN) {
        g_csr_src[r] = idx;              // self loop first
        g_cursor[idx] = r + 1;
    }
}

__global__ void csr_fill(const int* __restrict__ ei) {
    int i = blockIdx.x * blockDim.x + threadIdx.x;
    if (i >= EE) return;
    int s = ei[i], d = ei[EE + i];
    int pos = atomicAdd(&g_cursor[d], 1);
    g_csr_src[pos] = s;
}

// ---------------- conv1 GEMM: x[N,128] x W[128,64] -> g_h, g_as, g_ad --------
// 64 nodes/block, 256 threads (tx=16 colgroups, ty=16 -> 2 node-pairs each).
// 24 warps/SM at 3 blocks/SM -> 37.5% occupancy (vs 16% at 128 threads).
__global__ void gemm_conv1(const float* __restrict__ A,
                           const float* __restrict__ W,
                           const float* __restrict__ av,
                           const float* __restrict__ adv) {
    extern __shared__ float sm[];
    float* Ws  = sm;                 // [128][64]
    float* Ast = sm + KIN * 64;      // [128][66]
    const int AST = 66;

    int tid = threadIdx.x;
    int tx = tid & 15;
    int ty = tid >> 4;               // 0..15

    for (int i = tid; i < KIN * 64; i += 256) Ws[i] = W[i];
    int nbase = blockIdx.x * 64;
    for (int i = tid; i < 64 * KIN; i += 256) {
        int node = i / KIN, k = i % KIN;
        int n = nbase + node;
        Ast[k * AST + node] = (n < NN) ? A[n * KIN + k] : 0.f;
    }
    __syncthreads();

    ull acc[2][4];
    #pragma unroll
    for (int p = 0; p < 2; p++)
        #pragma unroll
        for (int c = 0; c < 4; c++) acc[p][c] = 0ull;

    #pragma unroll 4
    for (int k = 0; k < KIN; k++) {
        float4 wv = *(const float4*)&Ws[k * 64 + tx * 4];
        ull w0 = pack2(wv.x), w1 = pack2(wv.y), w2 = pack2(wv.z), w3 = pack2(wv.w);
        #pragma unroll
        for (int p = 0; p < 2; p++) {
            int pair = ty + 16 * p;
            ull ap = *(const ull*)&Ast[k * AST + 2 * pair];
            ffma2(acc[p][0], ap, w0);
            ffma2(acc[p][1], ap, w1);
            ffma2(acc[p][2], ap, w2);
            ffma2(acc[p][3], ap, w3);
        }
    }

    float4 a4  = *(const float4*)&av[tx * 4];
    float4 ad4 = *(const float4*)&adv[tx * 4];
    #pragma unroll
    for (int p = 0; p < 2; p++) {
        int n0 = nbase + 2 * (ty + 16 * p);
        bool ok0 = n0 < NN;
        bool ok1 = (n0 + 1) < NN;
        #pragma unroll
        for (int c = 0; c < 4; c++) {
            float v0, v1;
            unpack2(acc[p][c], v0, v1);
            int col = tx * 4 + c;
            if (ok0) g_h[n0 * 64 + col] = v0;
            if (ok1) g_h[(n0 + 1) * 64 + col] = v1;
        }
        ull pa = 0ull, pd = 0ull;
        ffma2(pa, acc[p][0], pack2(a4.x));  ffma2(pa, acc[p][1], pack2(a4.y));
        ffma2(pa, acc[p][2], pack2(a4.z));  ffma2(pa, acc[p][3], pack2(a4.w));
        ffma2(pd, acc[p][0], pack2(ad4.x)); ffma2(pd, acc[p][1], pack2(ad4.y));
        ffma2(pd, acc[p][2], pack2(ad4.z)); ffma2(pd, acc[p][3], pack2(ad4.w));
        #pragma unroll
        for (int off = 8; off > 0; off >>= 1) {
            pa = fadd2(pa, __shfl_xor_sync(0xffffffffu, pa, off));
            pd = fadd2(pd, __shfl_xor_sync(0xffffffffu, pd, off));
        }
        if (tx == 0) {
            float a0, a1, d0, d1;
            unpack2(pa, a0, a1);
            unpack2(pd, d0, d1);
            if (ok0) { g_as[n0] = a0; g_ad[n0] = d0; }
            if (ok1) { g_as[n0 + 1] = a1; g_ad[n0 + 1] = d1; }
        }
    }
}

// ---------------- layer GEMM: g_xp[N,64] x [convW|projW][64,128] -------------
__global__ void gemm_layer(const float* __restrict__ CW,
                           const float* __restrict__ PW,
                           const float* __restrict__ av,
                           const float* __restrict__ adv) {
    extern __shared__ float sm[];
    float* Ws  = sm;                 // [64][128]
    float* Ast = sm + HH * 128;      // [64][66]
    const int AST = 66;

    int tid = threadIdx.x;
    int tx = tid & 31;
    int ty = tid >> 5;

    for (int i = tid; i < HH * 128; i += 256) {
        int k = i >> 7, c = i & 127;
        Ws[i] = (c < 64) ? CW[k * 64 + c] : PW[k * 64 + (c - 64)];
    }
    int nbase = blockIdx.x * 64;
    for (int i = tid; i < 64 * HH; i += 256) {
        int node = i >> 6, k = i & 63;
        int n = nbase + node;
        Ast[k * AST + node] = (n < NN) ? g_xp[n * 64 + k] : 0.f;
    }
    __syncthreads();

    ull acc[4][4];
    #pragma unroll
    for (int p = 0; p < 4; p++)
        #pragma unroll
        for (int c = 0; c < 4; c++) acc[p][c] = 0ull;

    #pragma unroll 4
    for (int k = 0; k < HH; k++) {
        float4 wv = *(const float4*)&Ws[k * 128 + tx * 4];
        ull w0 = pack2(wv.x), w1 = pack2(wv.y), w2 = pack2(wv.z), w3 = pack2(wv.w);
        #pragma unroll
        for (int p = 0; p < 4; p++) {
            int pair = ty + 8 * p;
            ull ap = *(const ull*)&Ast[k * AST + 2 * pair];
            ffma2(acc[p][0], ap, w0);
            ffma2(acc[p][1], ap, w1);
            ffma2(acc[p][2], ap, w2);
            ffma2(acc[p][3], ap, w3);
        }
    }

    bool is_h = (tx < 16);
    float4 a4  = make_float4(0.f, 0.f, 0.f, 0.f);
    float4 ad4 = make_float4(0.f, 0.f, 0.f, 0.f);
    if (is_h) {
        a4  = *(const float4*)&av[tx * 4];
        ad4 = *(const float4*)&adv[tx * 4];
    }
    #pragma unroll
    for (int p = 0; p < 4; p++) {
        int n0 = nbase + 2 * (ty + 8 * p);
        bool ok0 = n0 < NN;
        bool ok1 = (n0 + 1) < NN;
        #pragma unroll
        for (int c = 0; c < 4; c++) {
            float v0, v1;
            unpack2(acc[p][c], v0, v1);
            int col = tx * 4 + c;
            float* dst = is_h ? &g_h[0] + n0 * 64 + col
                              : &g_res[0] + n0 * 64 + (col - 64);
            if (ok0) dst[0] = v0;
            if (ok1) dst[64] = v1;
        }
        ull pa = 0ull, pd = 0ull;
        if (is_h) {
            ffma2(pa, acc[p][0], pack2(a4.x));  ffma2(pa, acc[p][1], pack2(a4.y));
            ffma2(pa, acc[p][2], pack2(a4.z));  ffma2(pa, acc[p][3], pack2(a4.w));
            ffma2(pd, acc[p][0], pack2(ad4.x)); ffma2(pd, acc[p][1], pack2(ad4.y));
            ffma2(pd, acc[p][2], pack2(ad4.z)); ffma2(pd, acc[p][3], pack2(ad4.w));
        }
        #pragma unroll
        for (int off = 16; off > 0; off >>= 1) {
            pa = fadd2(pa, __shfl_xor_sync(0xffffffffu, pa, off));
            pd = fadd2(pd, __shfl_xor_sync(0xffffffffu, pd, off));
        }
        if (tx == 0) {
            float a0, a1, d0, d1;
            unpack2(pa, a0, a1);
            unpack2(pd, d0, d1);
            if (ok0) { g_as[n0] = a0; g_ad[n0] = d0; }
            if (ok1) { g_as[n0 + 1] = a1; g_ad[n0 + 1] = d1; }
        }
    }
}

// ---------------- fused GAT: edge weights + aggregation + epilogue -----------
// Round-11 body: plain unroll-4, compiler-scheduled (measured best).
template <int FIRST, int POOL>
__global__ void gat_agg(const float* __restrict__ cb,
                        const float* __restrict__ pb,
                        const float* __restrict__ bg, const float* __restrict__ bb,
                        const float* __restrict__ bm, const float* __restrict__ bv) {
    __shared__ float sp[POOL ? 512 : 1];
    int warp = (blockIdx.x * blockDim.x + threadIdx.x) >> 5;
    int lane = threadIdx.x & 31;
    int beg = g_rowptr[warp];
    int end = g_rowptr[warp + 1];
    float adv = g_ad[warp];

    float s = 0.f;
    float2 acc = make_float2(0.f, 0.f);
    int j = beg;
    int fo = lane * 2;

    for (; j + 4 <= end; j += 4) {
        int s0 = g_csr_src[j];
        int s1 = g_csr_src[j + 1];
        int s2 = g_csr_src[j + 2];
        int s3 = g_csr_src[j + 3];
        float a0 = g_as[s0];
        float a1 = g_as[s1];
        float a2 = g_as[s2];
        float a3 = g_as[s3];
        float2 h0 = *(const float2*)&g_h[s0 * 64 + fo];
        float2 h1 = *(const float2*)&g_h[s1 * 64 + fo];
        float2 h2 = *(const float2*)&g_h[s2 * 64 + fo];
        float2 h3 = *(const float2*)&g_h[s3 * 64 + fo];
        float e0 = a0 + adv; e0 = e0 > 0.f ? e0 : 0.2f * e0;
        float e1 = a1 + adv; e1 = e1 > 0.f ? e1 : 0.2f * e1;
        float e2 = a2 + adv; e2 = e2 > 0.f ? e2 : 0.2f * e2;
        float e3 = a3 + adv; e3 = e3 > 0.f ? e3 : 0.2f * e3;
        float w0 = __expf(e0);
        float w1 = __expf(e1);
        float w2 = __expf(e2);
        float w3 = __expf(e3);
        s += (w0 + w1) + (w2 + w3);
        acc.x += w0 * h0.x; acc.y += w0 * h0.y;
        acc.x += w1 * h1.x; acc.y += w1 * h1.y;
        acc.x += w2 * h2.x; acc.y += w2 * h2.y;
        acc.x += w3 * h3.x; acc.y += w3 * h3.y;
    }
    for (; j < end; j++) {
        int s0 = g_csr_src[j];
        float e0 = g_as[s0] + adv; e0 = e0 > 0.f ? e0 : 0.2f * e0;
        float w0 = __expf(e0);
        float2 h0 = *(const float2*)&g_h[s0 * 64 + fo];
        s += w0;
        acc.x += w0 * h0.x;
        acc.y += w0 * h0.y;
    }

    float inv = 1.f / (s + 1e-16f);
    acc.x *= inv;
    acc.y *= inv;

    int f = fo;
    float v0 = fmaxf(acc.x + cb[f],     0.f);
    float v1 = fmaxf(acc.y + cb[f + 1], 0.f);
    v0 = (v0 - bm[f])     * rsqrtf(bv[f]     + 1e-5f) * bg[f]     + bb[f];
    v1 = (v1 - bm[f + 1]) * rsqrtf(bv[f + 1] + 1e-5f) * bg[f + 1] + bb[f + 1];
    if (!FIRST) {
        float2 rv = *(const float2*)&g_res[warp * 64 + f];
        v0 += rv.x + pb[f];
        v1 += rv.y + pb[f + 1];
    }
    *(float2*)&g_xp[warp * 64 + f] = make_float2(v0, v1);

    if (POOL) {
        int w = threadIdx.x >> 5;
        sp[w * 64 + f] = v0;
        sp[w * 64 + f + 1] = v1;
        __syncthreads();
        int t = threadIdx.x;
        if (t < 64) {
            float ps = 0.f;
            #pragma unroll
            for (int k = 0; k < 8; k++) ps += sp[k * 64 + t];
            g_poolp[blockIdx.x * 64 + t] = ps;
        }
    }
}

// ---------------- head: sum pool partials + MLP ------------------------------
__global__ void head_k(const float* __restrict__ hW1, const float* __restrict__ hb1,
                       const float* __restrict__ hg, const float* __restrict__ hb,
                       const float* __restrict__ hm, const float* __restrict__ hv,
                       const float* __restrict__ hW2, const float* __restrict__ hb2,
                       float* __restrict__ out) {
    __shared__ float part[512];
    __shared__ float gs[64];
    __shared__ float hs[32];
    int t = threadIdx.x;
    int f = t & 63, g = t >> 6;              // 8 batches
    float s = 0.f;
    for (int b = g; b < 6250; b += 8)
        s += g_poolp[b * 64 + f];
    part[t] = s;
    __syncthreads();
    if (t < 64) {
        float tot = 0.f;
        #pragma unroll
        for (int k = 0; k < 8; k++) tot += part[k * 64 + t];
        gs[t] = tot * (1.0f / NN);
    }
    __syncthreads();
    if (t < 32) {
        float acc = hb1[t];
        #pragma unroll 16
        for (int ff = 0; ff < 64; ff++) acc += gs[ff] * hW1[ff * 32 + t];
        acc = fmaxf(acc, 0.f);
        acc = (acc - hm[t]) * rsqrtf(hv[t] + 1e-5f) * hg[t] + hb[t];
        hs[t] = acc * hW2[t];
    }
    __syncthreads();
    if (t == 0) {
        float ss = 0.f;
        for (int j = 0; j < 32; j++) ss += hs[j];
        out[0] = ss + hb2[0];
    }
}

// ---------------- launch ----------------------------------------------------
extern "C" void kernel_launch(void* const* d_in, const int* in_sizes, int n_in,
                              void* d_out, int out_size) {
    const float* x        = (const float*)d_in[0];
    const int*   ei       = (const int*)d_in[1];
    const float* conv1_W  = (const float*)d_in[2];
    const float* conv1_as = (const float*)d_in[3];
    const float* conv1_ad = (const float*)d_in[4];
    const float* conv1_b  = (const float*)d_in[5];
    const float* convW    = (const float*)d_in[6];
    const float* conv_as  = (const float*)d_in[7];
    const float* conv_ad  = (const float*)d_in[8];
    const float* conv_b   = (const float*)d_in[9];
    const float* bn_g     = (const float*)d_in[10];
    const float* bn_b     = (const float*)d_in[11];
    const float* bn_m     = (const float*)d_in[12];
    const float* bn_v     = (const float*)d_in[13];
    const float* projW    = (const float*)d_in[14];
    const float* projb    = (const float*)d_in[15];
    const float* hW1      = (const float*)d_in[16];
    const float* hb1      = (const float*)d_in[17];
    const float* hbn_g    = (const float*)d_in[18];
    const float* hbn_b    = (const float*)d_in[19];
    const float* hbn_m    = (const float*)d_in[20];
    const float* hbn_v    = (const float*)d_in[21];
    const float* hW2      = (const float*)d_in[22];
    const float* hb2      = (const float*)d_in[23];
    float* out = (float*)d_out;

    const int NB_E    = (EE + 255) / 256;               // 3125
    const int NB_GEMM = (NN + 63) / 64;                 // 782
    const int NB_WARP = (NN * 32) / 256;                // 6250 (warp per node)

    const int SMEM_C1 = (KIN * 64 + KIN * 66) * 4;      // 66560 B
    const int SMEM_L  = (HH * 128 + HH * 66) * 4;       // 49664 B
    static int smem_set = 0;
    if (!smem_set) {
        cudaFuncSetAttribute(gemm_conv1, cudaFuncAttributeMaxDynamicSharedMemorySize, SMEM_C1);
        cudaFuncSetAttribute(gemm_layer, cudaFuncAttributeMaxDynamicSharedMemorySize, SMEM_L);
        smem_set = 1;
    }

    // ---- CSR build + conv1 GEMM interleaved (gemm_conv1 in profile slot 4) --
    deg_init<<<(NN + 256) / 256, 256>>>();
    deg_count<<<NB_E, 256>>>(ei);
    scan_local<<<NSCAN_BLK, 256>>>();
    gemm_conv1<<<NB_GEMM, 256, SMEM_C1>>>(x, conv1_W, conv1_as, conv1_ad);
    scan_tot<<<1, 256>>>();
    scan_add<<<NSCAN_BLK, 256>>>();
    csr_fill<<<NB_E, 256>>>(ei);

    // ---- conv1 aggregation ----
    gat_agg<1, 0><<<NB_WARP, 256>>>(conv1_b, nullptr, bn_g, bn_b, bn_m, bn_v);

    // ---- conv2..conv5 (pool fused into last agg) ----
    for (int l = 0; l < 4; l++) {
        gemm_layer<<<NB_GEMM, 256, SMEM_L>>>(convW + l * 4096, projW + l * 4096,
                                             conv_as + l * 64, conv_ad + l * 64);
        if (l < 3)
            gat_agg<0, 0><<<NB_WARP, 256>>>(conv_b + l * 64, projb + l * 64,
                                            bn_g + (l + 1) * 64, bn_b + (l + 1) * 64,
                                            bn_m + (l + 1) * 64, bn_v + (l + 1) * 64);
        else
            gat_agg<0, 1><<<NB_WARP, 256>>>(conv_b + l * 64, projb + l * 64,
                                            bn_g + (l + 1) * 64, bn_b + (l + 1) * 64,
                                            bn_m + (l + 1) * 64, bn_v + (l + 1) * 64);
    }

    // ---- head ----
    head_k<<<1, 512>>>(hW1, hb1, hbn_g, hbn_b, hbn_m, hbn_v, hW2, hb2, out);
}